// round 1
// baseline (speedup 1.0000x reference)
#include <cuda_runtime.h>
#include <cuda_bf16.h>
#include <cstdint>
#include <cstdio>

// Problem constants
#define BB   32
#define MAXN 1024
#define FF   215
#define HH   256
#define TT   8
#define LL   3
#define NN   (BB * MAXN)        // 32768
#define EE   524288
#define H3   (3 * HH)           // 768
#define KS   2064               // s row stride: 2048 msg cols + 8 cnt cols + 8 pad (mult of 16)

// ---------------------------------------------------------------------------
// Scratch (static __device__ globals — allocation-free per harness rules)
// ---------------------------------------------------------------------------
__device__ float g_h [ (size_t)NN * HH ];      // 33.5 MB  node hidden state
__device__ float g_s [ (size_t)NN * KS ];      // 270  MB  aggregated messages + counts
__device__ float g_m [ (size_t)NN * HH ];      // 33.5 MB  transformed messages
__device__ float g_gi[ (size_t)NN * H3 ];      // 100  MB  GRU input gates
__device__ float g_gh[ (size_t)NN * H3 ];      // 100  MB  GRU hidden gates
__device__ float g_Wb[ (size_t)LL * HH * KS ]; // 6.3  MB  folded message weights

// ---------------------------------------------------------------------------
// Weight prep: Wb[l][e][k]  (k<2048: Wm[l][k>>8][e][k&255]; 2048..2055: bm; pad 0)
// ---------------------------------------------------------------------------
__global__ void prep_wb_kernel(const float* __restrict__ Wm, const float* __restrict__ bm)
{
    int idx = blockIdx.x * blockDim.x + threadIdx.x;
    if (idx >= LL * HH * KS) return;
    int l   = idx / (HH * KS);
    int rem = idx % (HH * KS);
    int e   = rem / KS;
    int k   = rem % KS;
    float v = 0.0f;
    if (k < TT * HH) {
        int t = k >> 8, d = k & 255;
        v = Wm[((((size_t)l * TT + t) * HH) + e) * HH + d];
    } else if (k < TT * HH + TT) {
        int t = k - TT * HH;
        v = bm[((size_t)l * TT + t) * HH + e];
    }
    g_Wb[idx] = v;
}

// ---------------------------------------------------------------------------
// SGEMM NT: C[M x Nc] = A[M x K] @ B[Nc x K]^T (+ bias[Nc])
// Row-major, K contiguous in both A and B. M, Nc multiples of 128.
// 128x128x16 tiles, 256 threads, 8x8 register tile.
// ---------------------------------------------------------------------------
#define BM 128
#define BN 128
#define BK 16
#define SPAD 132   // smem row stride: mult of 4 (float4 align), 2-way store conflict only

__global__ void __launch_bounds__(256, 2)
sgemm_nt(const float* __restrict__ A, const float* __restrict__ B,
         const float* __restrict__ bias, float* __restrict__ C,
         int M, int Nc, int K, int lda, int ldb, int ldc)
{
    __shared__ __align__(16) float As[BK * SPAD];
    __shared__ __align__(16) float Bs[BK * SPAD];

    const int tid = threadIdx.x;
    const int tx  = tid & 15;        // 0..15 -> column group
    const int ty  = tid >> 4;        // 0..15 -> row group
    const int bm0 = blockIdx.y * BM;
    const int bn0 = blockIdx.x * BN;

    float acc[8][8];
#pragma unroll
    for (int i = 0; i < 8; i++)
#pragma unroll
        for (int j = 0; j < 8; j++) acc[i][j] = 0.0f;

    for (int k0 = 0; k0 < K; k0 += BK) {
        // Load A tile (128x16), coalesced along K, store transposed As[k][row]
#pragma unroll
        for (int i = 0; i < 8; i++) {
            int l  = tid + i * 256;
            int r  = l >> 4;
            int kk = l & 15;
            int kg = k0 + kk;
            As[kk * SPAD + r] = (kg < K) ? A[(size_t)(bm0 + r) * lda + kg] : 0.0f;
        }
#pragma unroll
        for (int i = 0; i < 8; i++) {
            int l  = tid + i * 256;
            int r  = l >> 4;
            int kk = l & 15;
            int kg = k0 + kk;
            Bs[kk * SPAD + r] = (kg < K) ? B[(size_t)(bn0 + r) * ldb + kg] : 0.0f;
        }
        __syncthreads();

#pragma unroll
        for (int kk = 0; kk < BK; kk++) {
            float a[8], b[8];
            *(float4*)&a[0] = *(const float4*)&As[kk * SPAD + ty * 8];
            *(float4*)&a[4] = *(const float4*)&As[kk * SPAD + ty * 8 + 4];
            *(float4*)&b[0] = *(const float4*)&Bs[kk * SPAD + tx * 8];
            *(float4*)&b[4] = *(const float4*)&Bs[kk * SPAD + tx * 8 + 4];
#pragma unroll
            for (int i = 0; i < 8; i++)
#pragma unroll
                for (int j = 0; j < 8; j++)
                    acc[i][j] += a[i] * b[j];
        }
        __syncthreads();
    }

#pragma unroll
    for (int i = 0; i < 8; i++) {
        int row = bm0 + ty * 8 + i;
#pragma unroll
        for (int j = 0; j < 8; j++) {
            int col = bn0 + tx * 8 + j;
            float v = acc[i][j];
            if (bias) v += bias[col];
            C[(size_t)row * ldc + col] = v;
        }
    }
}

// ---------------------------------------------------------------------------
// Scatter: one warp per edge. s[dst, type] += h[src]; cnt[dst, type] += 1
// Uses vector reduction (red.global.add.v4.f32, sm_90+).
// ---------------------------------------------------------------------------
__device__ __forceinline__ void red_add_v4(float* p, float4 v)
{
    asm volatile("red.global.add.v4.f32 [%0], {%1, %2, %3, %4};"
                 :: "l"(p), "f"(v.x), "f"(v.y), "f"(v.z), "f"(v.w)
                 : "memory");
}

__global__ void scatter_kernel(const int* __restrict__ edge_index,
                               const int* __restrict__ edge_type)
{
    int gw   = (blockIdx.x * blockDim.x + threadIdx.x) >> 5;   // global warp = edge
    int lane = threadIdx.x & 31;
    if (gw >= EE) return;
    int src = edge_index[gw];
    int dst = edge_index[EE + gw];
    int t   = edge_type[gw];

    const float4* hp = (const float4*)(g_h + (size_t)src * HH);
    float* sp = g_s + (size_t)dst * KS + t * HH;

    float4 v0 = hp[lane];
    float4 v1 = hp[lane + 32];
    red_add_v4(sp + lane * 4, v0);
    red_add_v4(sp + 128 + lane * 4, v1);
    if (lane == 0)
        atomicAdd(g_s + (size_t)dst * KS + TT * HH + t, 1.0f);
}

// ---------------------------------------------------------------------------
// GRU gate elementwise: h = (1-z)*tanh(i_n + r*h_n) + z*h
// ---------------------------------------------------------------------------
__device__ __forceinline__ float sigmoidf_(float x) { return 1.0f / (1.0f + expf(-x)); }

__global__ void gru_kernel()
{
    int idx = blockIdx.x * blockDim.x + threadIdx.x;
    if (idx >= NN * HH) return;
    int n = idx >> 8;
    int j = idx & 255;
    const float* gi = g_gi + (size_t)n * H3;
    const float* gh = g_gh + (size_t)n * H3;
    float r  = sigmoidf_(gi[j]        + gh[j]);
    float z  = sigmoidf_(gi[HH + j]   + gh[HH + j]);
    float ng = tanhf   (gi[2*HH + j] + r * gh[2*HH + j]);
    float hv = g_h[idx];
    g_h[idx] = (1.0f - z) * ng + z * hv;
}

// ---------------------------------------------------------------------------
// Readout: out[b][j] = sum_n h[b*MAXN + n][j]   (split over 8 chunks + atomic)
// ---------------------------------------------------------------------------
__global__ void readout_kernel(float* __restrict__ out)
{
    int b = blockIdx.x;
    int c = blockIdx.y;          // 0..7
    int j = threadIdx.x;         // 0..255
    const float* hp = g_h + ((size_t)b * MAXN + (size_t)c * 128) * HH + j;
    float sum = 0.0f;
#pragma unroll 8
    for (int n = 0; n < 128; n++) sum += hp[(size_t)n * HH];
    atomicAdd(&out[b * HH + j], sum);
}

// ---------------------------------------------------------------------------
// Launch
// ---------------------------------------------------------------------------
extern "C" void kernel_launch(void* const* d_in, const int* in_sizes, int n_in,
                              void* d_out, int out_size)
{
    const float* node_features = (const float*)d_in[0];   // (B, MAXN, F)
    const int*   edge_index    = (const int*)  d_in[1];   // (2, E)
    const int*   edge_type     = (const int*)  d_in[2];   // (E,)
    const float* Wp  = (const float*)d_in[3];             // (H, F)
    const float* bp  = (const float*)d_in[4];             // (H,)
    const float* Wm  = (const float*)d_in[5];             // (L, T, H, H)
    const float* bm  = (const float*)d_in[6];             // (L, T, H)
    const float* Wih = (const float*)d_in[7];             // (L, 3H, H)
    const float* Whh = (const float*)d_in[8];             // (L, 3H, H)
    const float* bih = (const float*)d_in[9];             // (L, 3H)
    const float* bhh = (const float*)d_in[10];            // (L, 3H)
    float* out = (float*)d_out;                           // (B, H)

    // Resolve device scratch addresses
    float *p_h, *p_s, *p_m, *p_gi, *p_gh, *p_Wb;
    cudaGetSymbolAddress((void**)&p_h,  g_h);
    cudaGetSymbolAddress((void**)&p_s,  g_s);
    cudaGetSymbolAddress((void**)&p_m,  g_m);
    cudaGetSymbolAddress((void**)&p_gi, g_gi);
    cudaGetSymbolAddress((void**)&p_gh, g_gh);
    cudaGetSymbolAddress((void**)&p_Wb, g_Wb);

    // 0) Fold message weights + biases into Wb (per call; deterministic)
    {
        int total = LL * HH * KS;
        prep_wb_kernel<<<(total + 255) / 256, 256>>>(Wm, bm);
    }

    // 1) Input projection: h = X @ Wp^T + bp   (M=N, Nc=H, K=F)
    {
        dim3 grid(HH / BN, NN / BM);
        sgemm_nt<<<grid, 256>>>(node_features, Wp, bp, p_h,
                                NN, HH, FF, FF, FF, HH);
    }

    // 2) Layers
    for (int l = 0; l < LL; l++) {
        // 2a) zero aggregation buffer
        cudaMemsetAsync(p_s, 0, (size_t)NN * KS * sizeof(float));

        // 2b) scatter: s[dst,t] += h[src], cnt[dst,t]++
        {
            int warps = EE;
            int threads = 256;
            int blocks = (warps * 32) / threads;
            scatter_kernel<<<blocks, threads>>>(edge_index, edge_type);
        }

        // 2c) m = s @ Wb[l]^T   (K = 2064 folds Wm and cnt*bm)
        {
            dim3 grid(HH / BN, NN / BM);
            sgemm_nt<<<grid, 256>>>(p_s, p_Wb + (size_t)l * HH * KS, nullptr, p_m,
                                    NN, HH, KS, KS, KS, HH);
        }

        // 2d) gi = m @ Wih[l]^T + bih[l]
        {
            dim3 grid(H3 / BN, NN / BM);
            sgemm_nt<<<grid, 256>>>(p_m, Wih + (size_t)l * H3 * HH,
                                    bih + (size_t)l * H3, p_gi,
                                    NN, H3, HH, HH, HH, H3);
        }
        // 2e) gh = h @ Whh[l]^T + bhh[l]
        {
            dim3 grid(H3 / BN, NN / BM);
            sgemm_nt<<<grid, 256>>>(p_h, Whh + (size_t)l * H3 * HH,
                                    bhh + (size_t)l * H3, p_gh,
                                    NN, H3, HH, HH, HH, H3);
        }
        // 2f) GRU gates (updates h in place)
        gru_kernel<<<(NN * HH) / 256, 256>>>();
    }

    // 3) Readout
    cudaMemsetAsync(out, 0, (size_t)BB * HH * sizeof(float));
    {
        dim3 grid(BB, 8);
        readout_kernel<<<grid, 256>>>(out);
    }
}

// round 3
// speedup vs baseline: 2.1383x; 2.1383x over previous
#include <cuda_runtime.h>
#include <cuda_bf16.h>
#include <cstdint>

// Problem constants
#define BB   32
#define MAXN 1024
#define FF   215
#define HH   256
#define TT   8
#define LL   3
#define NN   (BB * MAXN)        // 32768
#define EE   524288
#define H3   (3 * HH)           // 768
#define KS   2112               // s row stride: 2048 msg + 8 cnt + 56 pad (mult of 64)

// ---------------------------------------------------------------------------
// Scratch (static __device__ globals — allocation-free per harness rules)
// ---------------------------------------------------------------------------
__device__ __align__(128) float g_h [ (size_t)NN * HH ];
__device__ __align__(128) float g_s [ (size_t)NN * KS ];   // 277 MB
__device__ __align__(128) float g_m [ (size_t)NN * HH ];
__device__ __align__(128) float g_gi[ (size_t)NN * H3 ];
__device__ __align__(128) float g_gh[ (size_t)NN * H3 ];
__device__ __align__(128) float g_Wb[ (size_t)LL * HH * KS ];
// bf16 hi/lo split weights
__device__ __align__(128) __nv_bfloat16 g_Wbh [ (size_t)LL * HH * KS ];
__device__ __align__(128) __nv_bfloat16 g_Wbl [ (size_t)LL * HH * KS ];
__device__ __align__(128) __nv_bfloat16 g_Wph [ 256 * 256 ];
__device__ __align__(128) __nv_bfloat16 g_Wpl [ 256 * 256 ];
__device__ __align__(128) __nv_bfloat16 g_Wihh[ (size_t)LL * H3 * HH ];
__device__ __align__(128) __nv_bfloat16 g_Wihl[ (size_t)LL * H3 * HH ];
__device__ __align__(128) __nv_bfloat16 g_Whhh[ (size_t)LL * H3 * HH ];
__device__ __align__(128) __nv_bfloat16 g_Whhl[ (size_t)LL * H3 * HH ];

// ---------------------------------------------------------------------------
// Helpers (base PTX only — no sm_103a-gated features)
// ---------------------------------------------------------------------------
__device__ __forceinline__ uint32_t smem_u32(const void* p) {
    uint32_t a;
    asm("{ .reg .u64 t; cvta.to.shared.u64 t, %1; cvt.u32.u64 %0, t; }" : "=r"(a) : "l"(p));
    return a;
}

__device__ __forceinline__ void ldsm4(uint32_t& r0, uint32_t& r1, uint32_t& r2, uint32_t& r3,
                                      uint32_t addr)
{
    asm volatile("ldmatrix.sync.aligned.m8n8.x4.shared.b16 {%0,%1,%2,%3}, [%4];"
                 : "=r"(r0), "=r"(r1), "=r"(r2), "=r"(r3) : "r"(addr));
}

__device__ __forceinline__ void mma_bf16(float* c, const uint32_t* a, uint32_t b0, uint32_t b1)
{
    asm volatile("mma.sync.aligned.m16n8k16.row.col.f32.bf16.bf16.f32 "
                 "{%0,%1,%2,%3}, {%4,%5,%6,%7}, {%8,%9}, {%0,%1,%2,%3};"
                 : "+f"(c[0]), "+f"(c[1]), "+f"(c[2]), "+f"(c[3])
                 : "r"(a[0]), "r"(a[1]), "r"(a[2]), "r"(a[3]), "r"(b0), "r"(b1));
}

// split fp32 pair -> packed bf16x2 hi + bf16x2 lo  (lo = x - bf16(x))
__device__ __forceinline__ void split2(float x0, float x1, uint32_t& h01, uint32_t& l01) {
    asm("cvt.rn.bf16x2.f32 %0, %1, %2;" : "=r"(h01) : "f"(x1), "f"(x0));   // lo-half = x0
    float h0 = __uint_as_float(h01 << 16);
    float h1 = __uint_as_float(h01 & 0xFFFF0000u);
    float l0 = x0 - h0;
    float l1 = x1 - h1;
    asm("cvt.rn.bf16x2.f32 %0, %1, %2;" : "=r"(l01) : "f"(l1), "f"(l0));
}

// ---------------------------------------------------------------------------
// mma_gemm: C[M x Nc] = A[M x K] @ B[Nc x K]^T (+ bias), fp32 via bf16 3-MMA split.
// Block tile 128x128, K-chunk 32. 8 warps (2m x 4n), warp tile 64x32.
// A fp32 -> inline hi/lo split. B pre-split bf16 hi/lo in gmem.
// grid = (Nc/128, M/128), 256 threads.
// ---------------------------------------------------------------------------
#define SA 40   // smem row stride in bf16 elements (80B) -> conflict-free ldmatrix

__global__ void __launch_bounds__(256)
mma_gemm(const float* __restrict__ A, int lda, int Ka, int avec,
         const __nv_bfloat16* __restrict__ Bh, const __nv_bfloat16* __restrict__ Bl, int ldb,
         const float* __restrict__ bias, float* __restrict__ C, int ldc, int nch)
{
    __shared__ __align__(16) __nv_bfloat16 sAh[128 * SA];
    __shared__ __align__(16) __nv_bfloat16 sAl[128 * SA];
    __shared__ __align__(16) __nv_bfloat16 sBh[128 * SA];
    __shared__ __align__(16) __nv_bfloat16 sBl[128 * SA];

    const int tid  = threadIdx.x;
    const int wid  = tid >> 5;
    const int lane = tid & 31;
    const int m0   = blockIdx.y * 128;
    const int n0   = blockIdx.x * 128;
    const int wm0  = (wid >> 2) * 64;   // warp m-origin in block
    const int wn0  = (wid & 3) * 32;    // warp n-origin in block

    float acc[4][4][4];
#pragma unroll
    for (int i = 0; i < 4; i++)
#pragma unroll
        for (int j = 0; j < 4; j++)
#pragma unroll
            for (int f = 0; f < 4; f++) acc[i][j][f] = 0.0f;

    // ldmatrix per-lane geometry
    const int g  = lane >> 3;
    const int ri = lane & 7;
    const int aRow = ri + ((g & 1) ? 8 : 0);
    const int aK   = (g & 2) ? 8 : 0;
    const int bRow = ri + ((g & 2) ? 8 : 0);
    const int bK   = (g & 1) ? 8 : 0;

    const uint32_t bAh = smem_u32(sAh), bAl = smem_u32(sAl);
    const uint32_t bBh = smem_u32(sBh), bBl = smem_u32(sBl);
    const uint32_t aOff = (uint32_t)(((wm0 + aRow) * SA + aK) * 2);
    const uint32_t bOff = (uint32_t)(((wn0 + bRow) * SA + bK) * 2);

    // gmem staging registers
    float a_ld[16];
    uint4 bh_ld[2], bl_ld[2];

    // ---- prefetch chunk 0
    {
        const int k0 = 0;
#pragma unroll
        for (int s = 0; s < 4; ++s) {
            int idx = s * 256 + tid;
            int r = idx >> 3, cc = (idx & 7) * 4;
            const float* ap = A + (size_t)(m0 + r) * lda + (k0 + cc);
            if (avec) {
                float4 v = *(const float4*)ap;
                a_ld[s*4+0] = v.x; a_ld[s*4+1] = v.y; a_ld[s*4+2] = v.z; a_ld[s*4+3] = v.w;
            } else {
                int kg = k0 + cc;
                a_ld[s*4+0] = (kg   < Ka) ? ap[0] : 0.0f;
                a_ld[s*4+1] = (kg+1 < Ka) ? ap[1] : 0.0f;
                a_ld[s*4+2] = (kg+2 < Ka) ? ap[2] : 0.0f;
                a_ld[s*4+3] = (kg+3 < Ka) ? ap[3] : 0.0f;
            }
        }
#pragma unroll
        for (int s = 0; s < 2; ++s) {
            int idx = s * 256 + tid;
            int r = idx >> 2, cc = (idx & 3) * 8;
            size_t go = (size_t)(n0 + r) * ldb + (k0 + cc);
            bh_ld[s] = *(const uint4*)(Bh + go);
            bl_ld[s] = *(const uint4*)(Bl + go);
        }
    }

    for (int c = 0; c < nch; ++c) {
        __syncthreads();
        // ---- store staged chunk into smem (A split inline)
#pragma unroll
        for (int s = 0; s < 4; ++s) {
            int idx = s * 256 + tid;
            int r = idx >> 3, cc = (idx & 7) * 4;
            uint32_t h01, l01, h23, l23;
            split2(a_ld[s*4+0], a_ld[s*4+1], h01, l01);
            split2(a_ld[s*4+2], a_ld[s*4+3], h23, l23);
            uint32_t off = (uint32_t)((r * SA + cc) * 2);
            asm volatile("st.shared.v2.b32 [%0], {%1,%2};" :: "r"(bAh + off), "r"(h01), "r"(h23) : "memory");
            asm volatile("st.shared.v2.b32 [%0], {%1,%2};" :: "r"(bAl + off), "r"(l01), "r"(l23) : "memory");
        }
#pragma unroll
        for (int s = 0; s < 2; ++s) {
            int idx = s * 256 + tid;
            int r = idx >> 2, cc = (idx & 3) * 8;
            uint32_t off = (uint32_t)((r * SA + cc) * 2);
            uint4 vh = bh_ld[s], vl = bl_ld[s];
            asm volatile("st.shared.v4.b32 [%0], {%1,%2,%3,%4};"
                         :: "r"(bBh + off), "r"(vh.x), "r"(vh.y), "r"(vh.z), "r"(vh.w) : "memory");
            asm volatile("st.shared.v4.b32 [%0], {%1,%2,%3,%4};"
                         :: "r"(bBl + off), "r"(vl.x), "r"(vl.y), "r"(vl.z), "r"(vl.w) : "memory");
        }
        __syncthreads();

        // ---- prefetch next chunk (overlaps with MMA below)
        if (c + 1 < nch) {
            const int k0 = (c + 1) * 32;
#pragma unroll
            for (int s = 0; s < 4; ++s) {
                int idx = s * 256 + tid;
                int r = idx >> 3, cc = (idx & 7) * 4;
                const float* ap = A + (size_t)(m0 + r) * lda + (k0 + cc);
                if (avec) {
                    float4 v = *(const float4*)ap;
                    a_ld[s*4+0] = v.x; a_ld[s*4+1] = v.y; a_ld[s*4+2] = v.z; a_ld[s*4+3] = v.w;
                } else {
                    int kg = k0 + cc;
                    a_ld[s*4+0] = (kg   < Ka) ? ap[0] : 0.0f;
                    a_ld[s*4+1] = (kg+1 < Ka) ? ap[1] : 0.0f;
                    a_ld[s*4+2] = (kg+2 < Ka) ? ap[2] : 0.0f;
                    a_ld[s*4+3] = (kg+3 < Ka) ? ap[3] : 0.0f;
                }
            }
#pragma unroll
            for (int s = 0; s < 2; ++s) {
                int idx = s * 256 + tid;
                int r = idx >> 2, cc = (idx & 3) * 8;
                size_t go = (size_t)(n0 + r) * ldb + (k0 + cc);
                bh_ld[s] = *(const uint4*)(Bh + go);
                bl_ld[s] = *(const uint4*)(Bl + go);
            }
        }

        // ---- compute: two k16 sub-steps, 3 split products each
#pragma unroll
        for (int kh = 0; kh < 32; kh += 16) {
            uint32_t Af[4][4], Bf[2][4];
            // A-hi fragments
#pragma unroll
            for (int i = 0; i < 4; ++i)
                ldsm4(Af[i][0], Af[i][1], Af[i][2], Af[i][3],
                      bAh + aOff + (uint32_t)((i * 16 * SA + kh) * 2));
            // B-lo fragments
#pragma unroll
            for (int j = 0; j < 2; ++j)
                ldsm4(Bf[j][0], Bf[j][1], Bf[j][2], Bf[j][3],
                      bBl + bOff + (uint32_t)((j * 16 * SA + kh) * 2));
            // Ah * Bl
#pragma unroll
            for (int i = 0; i < 4; ++i)
#pragma unroll
                for (int jj = 0; jj < 4; ++jj)
                    mma_bf16(acc[i][jj], Af[i], Bf[jj>>1][(jj&1)*2], Bf[jj>>1][(jj&1)*2+1]);
            // B-hi fragments (overwrite Bf)
#pragma unroll
            for (int j = 0; j < 2; ++j)
                ldsm4(Bf[j][0], Bf[j][1], Bf[j][2], Bf[j][3],
                      bBh + bOff + (uint32_t)((j * 16 * SA + kh) * 2));
            // Ah * Bh
#pragma unroll
            for (int i = 0; i < 4; ++i)
#pragma unroll
                for (int jj = 0; jj < 4; ++jj)
                    mma_bf16(acc[i][jj], Af[i], Bf[jj>>1][(jj&1)*2], Bf[jj>>1][(jj&1)*2+1]);
            // A-lo fragments (overwrite Af)
#pragma unroll
            for (int i = 0; i < 4; ++i)
                ldsm4(Af[i][0], Af[i][1], Af[i][2], Af[i][3],
                      bAl + aOff + (uint32_t)((i * 16 * SA + kh) * 2));
            // Al * Bh
#pragma unroll
            for (int i = 0; i < 4; ++i)
#pragma unroll
                for (int jj = 0; jj < 4; ++jj)
                    mma_bf16(acc[i][jj], Af[i], Bf[jj>>1][(jj&1)*2], Bf[jj>>1][(jj&1)*2+1]);
        }
    }

    // ---- epilogue: direct gmem store with optional bias
    const int qr = lane >> 2;          // row within 8
    const int qc = (lane & 3) * 2;     // col within 8
#pragma unroll
    for (int i = 0; i < 4; ++i) {
        int row = m0 + wm0 + i * 16 + qr;
#pragma unroll
        for (int jj = 0; jj < 4; ++jj) {
            int col = n0 + wn0 + jj * 8 + qc;
            float b0 = 0.0f, b1 = 0.0f;
            if (bias) { b0 = bias[col]; b1 = bias[col + 1]; }
            float2 v0 = make_float2(acc[i][jj][0] + b0, acc[i][jj][1] + b1);
            float2 v1 = make_float2(acc[i][jj][2] + b0, acc[i][jj][3] + b1);
            *(float2*)(C + (size_t)row * ldc + col)       = v0;
            *(float2*)(C + (size_t)(row + 8) * ldc + col) = v1;
        }
    }
}

// ---------------------------------------------------------------------------
// Weight prep
// ---------------------------------------------------------------------------
__global__ void prep_wb_kernel(const float* __restrict__ Wm, const float* __restrict__ bm)
{
    int idx = blockIdx.x * blockDim.x + threadIdx.x;
    if (idx >= LL * HH * KS) return;
    int l   = idx / (HH * KS);
    int rem = idx % (HH * KS);
    int e   = rem / KS;
    int k   = rem % KS;
    float v = 0.0f;
    if (k < TT * HH) {
        int t = k >> 8, d = k & 255;
        v = Wm[((((size_t)l * TT + t) * HH) + e) * HH + d];
    } else if (k < TT * HH + TT) {
        int t = k - TT * HH;
        v = bm[((size_t)l * TT + t) * HH + e];
    }
    g_Wb[idx] = v;
}

__global__ void prep_split(const float* __restrict__ src,
                           __nv_bfloat16* __restrict__ hi, __nv_bfloat16* __restrict__ lo,
                           int rows, int K, int Kb)
{
    int idx = blockIdx.x * blockDim.x + threadIdx.x;
    if (idx >= rows * Kb) return;
    int r = idx / Kb, k = idx - r * Kb;
    float x = (k < K) ? src[(size_t)r * K + k] : 0.0f;
    __nv_bfloat16 hb = __float2bfloat16(x);
    hi[idx] = hb;
    lo[idx] = __float2bfloat16(x - __bfloat162float(hb));
}

// ---------------------------------------------------------------------------
// Scatter: one warp per edge. s[dst, type] += h[src]; cnt[dst, type] += 1
// ---------------------------------------------------------------------------
__device__ __forceinline__ void red_add_v4(float* p, float4 v)
{
    asm volatile("red.global.add.v4.f32 [%0], {%1, %2, %3, %4};"
                 :: "l"(p), "f"(v.x), "f"(v.y), "f"(v.z), "f"(v.w) : "memory");
}

__global__ void scatter_kernel(const int* __restrict__ edge_index,
                               const int* __restrict__ edge_type)
{
    int gw   = (blockIdx.x * blockDim.x + threadIdx.x) >> 5;
    int lane = threadIdx.x & 31;
    if (gw >= EE) return;
    int src = edge_index[gw];
    int dst = edge_index[EE + gw];
    int t   = edge_type[gw];

    const float4* hp = (const float4*)(g_h + (size_t)src * HH);
    float* sp = g_s + (size_t)dst * KS + t * HH;

    float4 v0 = hp[lane];
    float4 v1 = hp[lane + 32];
    red_add_v4(sp + lane * 4, v0);
    red_add_v4(sp + 128 + lane * 4, v1);
    if (lane == 0)
        atomicAdd(g_s + (size_t)dst * KS + TT * HH + t, 1.0f);
}

// ---------------------------------------------------------------------------
// GRU gate elementwise
// ---------------------------------------------------------------------------
__device__ __forceinline__ float sigmoidf_(float x) { return 1.0f / (1.0f + expf(-x)); }

__global__ void gru_kernel()
{
    int idx = blockIdx.x * blockDim.x + threadIdx.x;
    if (idx >= NN * HH) return;
    int n = idx >> 8;
    int j = idx & 255;
    const float* gi = g_gi + (size_t)n * H3;
    const float* gh = g_gh + (size_t)n * H3;
    float r  = sigmoidf_(gi[j]        + gh[j]);
    float z  = sigmoidf_(gi[HH + j]   + gh[HH + j]);
    float ng = tanhf   (gi[2*HH + j] + r * gh[2*HH + j]);
    float hv = g_h[idx];
    g_h[idx] = (1.0f - z) * ng + z * hv;
}

// ---------------------------------------------------------------------------
// Readout
// ---------------------------------------------------------------------------
__global__ void readout_kernel(float* __restrict__ out)
{
    int b = blockIdx.x;
    int c = blockIdx.y;
    int j = threadIdx.x;
    const float* hp = g_h + ((size_t)b * MAXN + (size_t)c * 128) * HH + j;
    float sum = 0.0f;
#pragma unroll 8
    for (int n = 0; n < 128; n++) sum += hp[(size_t)n * HH];
    atomicAdd(&out[b * HH + j], sum);
}

// ---------------------------------------------------------------------------
// Launch
// ---------------------------------------------------------------------------
extern "C" void kernel_launch(void* const* d_in, const int* in_sizes, int n_in,
                              void* d_out, int out_size)
{
    const float* node_features = (const float*)d_in[0];
    const int*   edge_index    = (const int*)  d_in[1];
    const int*   edge_type     = (const int*)  d_in[2];
    const float* Wp  = (const float*)d_in[3];
    const float* bp  = (const float*)d_in[4];
    const float* Wm  = (const float*)d_in[5];
    const float* bm  = (const float*)d_in[6];
    const float* Wih = (const float*)d_in[7];
    const float* Whh = (const float*)d_in[8];
    const float* bih = (const float*)d_in[9];
    const float* bhh = (const float*)d_in[10];
    float* out = (float*)d_out;

    float *p_h, *p_s, *p_m, *p_gi, *p_gh, *p_Wb;
    __nv_bfloat16 *p_Wbh, *p_Wbl, *p_Wph, *p_Wpl, *p_Wihh, *p_Wihl, *p_Whhh, *p_Whhl;
    cudaGetSymbolAddress((void**)&p_h,   g_h);
    cudaGetSymbolAddress((void**)&p_s,   g_s);
    cudaGetSymbolAddress((void**)&p_m,   g_m);
    cudaGetSymbolAddress((void**)&p_gi,  g_gi);
    cudaGetSymbolAddress((void**)&p_gh,  g_gh);
    cudaGetSymbolAddress((void**)&p_Wb,  g_Wb);
    cudaGetSymbolAddress((void**)&p_Wbh, g_Wbh);
    cudaGetSymbolAddress((void**)&p_Wbl, g_Wbl);
    cudaGetSymbolAddress((void**)&p_Wph, g_Wph);
    cudaGetSymbolAddress((void**)&p_Wpl, g_Wpl);
    cudaGetSymbolAddress((void**)&p_Wihh, g_Wihh);
    cudaGetSymbolAddress((void**)&p_Wihl, g_Wihl);
    cudaGetSymbolAddress((void**)&p_Whhh, g_Whhh);
    cudaGetSymbolAddress((void**)&p_Whhl, g_Whhl);

    // 0) weight prep: fold + split
    {
        int total = LL * HH * KS;
        prep_wb_kernel<<<(total + 255) / 256, 256>>>(Wm, bm);
        prep_split<<<(total + 255) / 256, 256>>>(p_Wb, p_Wbh, p_Wbl, LL * HH, KS, KS);
        int tp = 256 * 256;
        prep_split<<<(tp + 255) / 256, 256>>>(Wp, p_Wph, p_Wpl, HH, FF, 256);
        int tg = LL * H3 * HH;
        prep_split<<<(tg + 255) / 256, 256>>>(Wih, p_Wihh, p_Wihl, LL * H3, HH, HH);
        prep_split<<<(tg + 255) / 256, 256>>>(Whh, p_Whhh, p_Whhl, LL * H3, HH, HH);
    }

    // 1) input projection: h = X @ Wp^T + bp  (K=215 -> 7 chunks of 32, guarded)
    {
        dim3 grid(HH / 128, NN / 128);
        mma_gemm<<<grid, 256>>>(node_features, FF, FF, 0,
                                p_Wph, p_Wpl, 256, bp, p_h, HH, 7);
    }

    // 2) layers
    for (int l = 0; l < LL; l++) {
        cudaMemsetAsync(p_s, 0, (size_t)NN * KS * sizeof(float));

        scatter_kernel<<<(EE * 32) / 256, 256>>>(edge_index, edge_type);

        // m = s @ Wb[l]^T  (K = 2112 folds type-linears + cnt*bm bias)
        {
            dim3 grid(HH / 128, NN / 128);
            mma_gemm<<<grid, 256>>>(p_s, KS, KS, 1,
                                    p_Wbh + (size_t)l * HH * KS,
                                    p_Wbl + (size_t)l * HH * KS, KS,
                                    (const float*)0, p_m, HH, KS / 32);
        }
        // gi = m @ Wih[l]^T + bih[l]
        {
            dim3 grid(H3 / 128, NN / 128);
            mma_gemm<<<grid, 256>>>(p_m, HH, HH, 1,
                                    p_Wihh + (size_t)l * H3 * HH,
                                    p_Wihl + (size_t)l * H3 * HH, HH,
                                    bih + (size_t)l * H3, p_gi, H3, 8);
        }
        // gh = h @ Whh[l]^T + bhh[l]
        {
            dim3 grid(H3 / 128, NN / 128);
            mma_gemm<<<grid, 256>>>(p_h, HH, HH, 1,
                                    p_Whhh + (size_t)l * H3 * HH,
                                    p_Whhl + (size_t)l * H3 * HH, HH,
                                    bhh + (size_t)l * H3, p_gh, H3, 8);
        }
        gru_kernel<<<(NN * HH) / 256, 256>>>();
    }

    // 3) readout
    cudaMemsetAsync(out, 0, (size_t)BB * HH * sizeof(float));
    {
        dim3 grid(BB, 8);
        readout_kernel<<<grid, 256>>>(out);
    }
}